// round 8
// baseline (speedup 1.0000x reference)
#include <cuda_runtime.h>
#include <cuda_bf16.h>
#include <cstdint>

#define BATCH 2
#define SEQ   2048
#define DMODEL 1024
#define NHEAD 16
#define HDIM  64
#define MROWS (BATCH * SEQ)
#define LN_EPS 1e-5f

typedef __nv_bfloat16 bf16;

// ---------------- device-global scratch (referenced ONLY from device code) ---
__device__ bf16 g_hb[(size_t)MROWS * DMODEL];
__device__ bf16 g_Wqb[DMODEL * DMODEL];
__device__ bf16 g_Wkb[DMODEL * DMODEL];
__device__ bf16 g_Wvb[DMODEL * DMODEL];
__device__ bf16 g_Wob[DMODEL * DMODEL];
__device__ bf16 g_qb[(size_t)MROWS * DMODEL];     // [B,H,S,hd]
__device__ bf16 g_kb[(size_t)MROWS * DMODEL];
__device__ bf16 g_vb[(size_t)MROWS * DMODEL];
__device__ bf16 g_attnb[(size_t)MROWS * DMODEL];  // [B*S, D]
__device__ int  g_mask_allones;

// ---------------- PTX helpers -------------------------------------------------
__device__ __forceinline__ uint32_t s2u(const void* p) {
    return (uint32_t)__cvta_generic_to_shared(p);
}
__device__ __forceinline__ void cp16(uint32_t saddr, const void* g) {
    asm volatile("cp.async.cg.shared.global [%0], [%1], 16;\n" :: "r"(saddr), "l"(g));
}
__device__ __forceinline__ void cp_commit() { asm volatile("cp.async.commit_group;\n"); }
__device__ __forceinline__ void cp_wait0()  { asm volatile("cp.async.wait_group 0;\n"); }
__device__ __forceinline__ void cp_wait1()  { asm volatile("cp.async.wait_group 1;\n"); }

__device__ __forceinline__ void ldsm4(uint32_t r[4], uint32_t addr) {
    asm volatile("ldmatrix.sync.aligned.m8n8.x4.shared.b16 {%0,%1,%2,%3}, [%4];\n"
                 : "=r"(r[0]), "=r"(r[1]), "=r"(r[2]), "=r"(r[3]) : "r"(addr));
}
__device__ __forceinline__ void ldsm4t(uint32_t r[4], uint32_t addr) {
    asm volatile("ldmatrix.sync.aligned.m8n8.x4.trans.shared.b16 {%0,%1,%2,%3}, [%4];\n"
                 : "=r"(r[0]), "=r"(r[1]), "=r"(r[2]), "=r"(r[3]) : "r"(addr));
}
__device__ __forceinline__ void mma16816(float c[4], const uint32_t a[4], const uint32_t b[2]) {
    asm volatile(
        "mma.sync.aligned.m16n8k16.row.col.f32.bf16.bf16.f32 "
        "{%0,%1,%2,%3}, {%4,%5,%6,%7}, {%8,%9}, {%0,%1,%2,%3};\n"
        : "+f"(c[0]), "+f"(c[1]), "+f"(c[2]), "+f"(c[3])
        : "r"(a[0]), "r"(a[1]), "r"(a[2]), "r"(a[3]), "r"(b[0]), "r"(b[1]));
}
__device__ __forceinline__ uint32_t pack_bf2(float lo, float hi) {
    __nv_bfloat162 h = __floats2bfloat162_rn(lo, hi);
    return *reinterpret_cast<uint32_t*>(&h);
}
__device__ __forceinline__ int sw64(int row, int c16)  { return (row << 6) + ((c16 ^ ((row >> 1) & 3)) << 4); }
__device__ __forceinline__ int sw128(int row, int c16) { return (row << 7) + ((c16 ^ (row & 7)) << 4); }

// ---------------- layernorm -> bf16 ------------------------------------------
__global__ __launch_bounds__(256) void ln_kernel(const float* __restrict__ x,
                                                 const float* __restrict__ gamma,
                                                 const float* __restrict__ beta) {
    int row = blockIdx.x;
    const float* xr = x + (size_t)row * DMODEL;
    int c0 = threadIdx.x * 4;
    float4 f = *(const float4*)(xr + c0);
    float s  = f.x + f.y + f.z + f.w;
    float sq = f.x * f.x + f.y * f.y + f.z * f.z + f.w * f.w;
#pragma unroll
    for (int o = 16; o; o >>= 1) {
        s  += __shfl_xor_sync(0xffffffffu, s, o);
        sq += __shfl_xor_sync(0xffffffffu, sq, o);
    }
    __shared__ float ss[8], ssq[8];
    int w = threadIdx.x >> 5, l = threadIdx.x & 31;
    if (l == 0) { ss[w] = s; ssq[w] = sq; }
    __syncthreads();
    if (w == 0) {
        s  = (l < 8) ? ss[l]  : 0.f;
        sq = (l < 8) ? ssq[l] : 0.f;
#pragma unroll
        for (int o = 4; o; o >>= 1) {
            s  += __shfl_xor_sync(0xffffffffu, s, o);
            sq += __shfl_xor_sync(0xffffffffu, sq, o);
        }
        if (l == 0) { ss[0] = s; ssq[0] = sq; }
    }
    __syncthreads();
    float mu  = ss[0] * (1.f / DMODEL);
    float var = ssq[0] * (1.f / DMODEL) - mu * mu;
    float inv = rsqrtf(var + LN_EPS);
    float4 g = *(const float4*)(gamma + c0);
    float4 b = *(const float4*)(beta + c0);
    uint2 o;
    o.x = pack_bf2((f.x - mu) * inv * g.x + b.x, (f.y - mu) * inv * g.y + b.y);
    o.y = pack_bf2((f.z - mu) * inv * g.z + b.z, (f.w - mu) * inv * g.w + b.w);
    *(uint2*)&g_hb[(size_t)row * DMODEL + c0] = o;
}

// ---------------- weight fp32 -> bf16 (+ mask flag init) -----------------------
__global__ __launch_bounds__(256) void cvt_w_kernel(const float* __restrict__ Wq,
                                                    const float* __restrict__ Wk,
                                                    const float* __restrict__ Wv,
                                                    const float* __restrict__ Wo) {
    if (blockIdx.x == 0 && blockIdx.y == 0 && threadIdx.x == 0) g_mask_allones = 1;
    const float* src; bf16* dst;
    if (blockIdx.y == 0)      { src = Wq; dst = g_Wqb; }
    else if (blockIdx.y == 1) { src = Wk; dst = g_Wkb; }
    else if (blockIdx.y == 2) { src = Wv; dst = g_Wvb; }
    else                      { src = Wo; dst = g_Wob; }
    int i = (blockIdx.x * 256 + threadIdx.x) * 4;
    float4 f = *(const float4*)(src + i);
    uint2 o;
    o.x = pack_bf2(f.x, f.y);
    o.y = pack_bf2(f.z, f.w);
    *(uint2*)&dst[i] = o;
}

// ---------------- mask all-ones scan ------------------------------------------
__global__ __launch_bounds__(256) void mask_scan_kernel(const int4* __restrict__ m4) {
    int base = blockIdx.x * (256 * 8) + threadIdx.x;
    int4 t[8];
#pragma unroll
    for (int u = 0; u < 8; u++) t[u] = m4[base + u * 256];
    int ok = 1;
#pragma unroll
    for (int u = 0; u < 8; u++)
        ok &= (t[u].x != 0) & (t[u].y != 0) & (t[u].z != 0) & (t[u].w != 0);
    if (!ok) atomicAnd(&g_mask_allones, 0);
}

// ---------------- shared GEMM mainloop (bf16 HMMA, 3-stage cp.async) -----------
__device__ __forceinline__ void gemm_ml(const bf16* __restrict__ A,
                                        const bf16* __restrict__ W,
                                        int rowBase, int colBase,
                                        bf16 (*As)[128 * 32], bf16 (*Bs)[128 * 32],
                                        float acc[4][4][4]) {
    int tid = threadIdx.x, lane = tid & 31, warp = tid >> 5;
    int wm = warp >> 2, wn = warp & 3;
    int lrow = tid >> 2, lc = tid & 3;
    int j = lane >> 3, l7 = lane & 7;

#define GEMM_STAGE(st, kb)                                                         \
    {                                                                              \
        _Pragma("unroll")                                                          \
        for (int p = 0; p < 2; p++) {                                              \
            int row = lrow + p * 64;                                               \
            cp16(s2u(As[st]) + sw64(row, lc),                                      \
                 A + (size_t)(rowBase + row) * DMODEL + (kb) * 32 + lc * 8);       \
            cp16(s2u(Bs[st]) + sw64(row, lc),                                      \
                 W + (size_t)(colBase + row) * DMODEL + (kb) * 32 + lc * 8);       \
        }                                                                          \
    }

    GEMM_STAGE(0, 0); cp_commit();
    GEMM_STAGE(1, 1); cp_commit();
    cp_wait1();          // stage 0 ready
    __syncthreads();

#pragma unroll 1
    for (int kb = 0; kb < 32; kb++) {
        int st = kb % 3;
        if (kb + 2 < 32) { GEMM_STAGE((kb + 2) % 3, kb + 2); cp_commit(); }
        uint32_t ab = s2u(As[st]), bb_ = s2u(Bs[st]);
#pragma unroll
        for (int kt = 0; kt < 2; kt++) {
            uint32_t a[4][4];
#pragma unroll
            for (int mt = 0; mt < 4; mt++) {
                int row = wm * 64 + mt * 16 + ((j & 1) << 3) + l7;
                ldsm4(a[mt], ab + sw64(row, kt * 2 + (j >> 1)));
            }
            uint32_t b[4][2];
#pragma unroll
            for (int np = 0; np < 2; np++) {
                int row = wn * 32 + np * 16 + ((j >> 1) << 3) + l7;
                uint32_t r[4];
                ldsm4(r, bb_ + sw64(row, kt * 2 + (j & 1)));
                b[2 * np][0] = r[0]; b[2 * np][1] = r[1];
                b[2 * np + 1][0] = r[2]; b[2 * np + 1][1] = r[3];
            }
#pragma unroll
            for (int mt = 0; mt < 4; mt++)
#pragma unroll
                for (int nt = 0; nt < 4; nt++)
                    mma16816(acc[mt][nt], a[mt], b[nt]);
        }
        if (kb < 31) {
            if (kb + 2 < 32) cp_wait1(); else cp_wait0();
            __syncthreads();
        }
    }
#undef GEMM_STAGE
}

// ---------------- QKV GEMM: bf16 out reordered to [B,H,S,hd] -------------------
__global__ __launch_bounds__(256) void gemm_qkv(const float* __restrict__ bq,
                                                const float* __restrict__ bk,
                                                const float* __restrict__ bv) {
    __shared__ bf16 As[3][128 * 32], Bs[3][128 * 32];
    const bf16* W; const float* bias; bf16* C;
    if (blockIdx.z == 0)      { W = g_Wqb; bias = bq; C = g_qb; }
    else if (blockIdx.z == 1) { W = g_Wkb; bias = bk; C = g_kb; }
    else                      { W = g_Wvb; bias = bv; C = g_vb; }

    float acc[4][4][4];
#pragma unroll
    for (int i = 0; i < 4; i++)
#pragma unroll
        for (int k = 0; k < 4; k++)
#pragma unroll
            for (int r = 0; r < 4; r++) acc[i][k][r] = 0.f;

    int rowBase = blockIdx.y * 128, colBase = blockIdx.x * 128;
    gemm_ml(g_hb, W, rowBase, colBase, As, Bs, acc);

    int lane = threadIdx.x & 31, warp = threadIdx.x >> 5;
    int wm = warp >> 2, wn = warp & 3;
    int r4 = lane >> 2, c2 = (lane & 3) * 2;
#pragma unroll
    for (int mt = 0; mt < 4; mt++)
#pragma unroll
        for (int nt = 0; nt < 4; nt++)
#pragma unroll
            for (int h = 0; h < 2; h++) {
                int m = rowBase + wm * 64 + mt * 16 + r4 + h * 8;
                int n = colBase + wn * 32 + nt * 8 + c2;
                float v0 = acc[mt][nt][h * 2 + 0] + bias[n];
                float v1 = acc[mt][nt][h * 2 + 1] + bias[n + 1];
                int bbi = m >> 11, s = m & 2047, hh = n >> 6, d = n & 63;
                *(uint32_t*)&C[(((size_t)(bbi * NHEAD + hh) * SEQ + s) << 6) + d] =
                    pack_bf2(v0, v1);
            }
}

// ---------------- out GEMM: fp32 out = attn @ Wo^T + bo + residual -------------
__global__ __launch_bounds__(256) void gemm_out(const float* __restrict__ bo,
                                                const float* __restrict__ resid,
                                                float* __restrict__ outp) {
    __shared__ bf16 As[3][128 * 32], Bs[3][128 * 32];
    float acc[4][4][4];
#pragma unroll
    for (int i = 0; i < 4; i++)
#pragma unroll
        for (int k = 0; k < 4; k++)
#pragma unroll
            for (int r = 0; r < 4; r++) acc[i][k][r] = 0.f;

    int rowBase = blockIdx.y * 128, colBase = blockIdx.x * 128;
    gemm_ml(g_attnb, g_Wob, rowBase, colBase, As, Bs, acc);

    int lane = threadIdx.x & 31, warp = threadIdx.x >> 5;
    int wm = warp >> 2, wn = warp & 3;
    int r4 = lane >> 2, c2 = (lane & 3) * 2;
#pragma unroll
    for (int mt = 0; mt < 4; mt++)
#pragma unroll
        for (int nt = 0; nt < 4; nt++)
#pragma unroll
            for (int h = 0; h < 2; h++) {
                int m = rowBase + wm * 64 + mt * 16 + r4 + h * 8;
                int n = colBase + wn * 32 + nt * 8 + c2;
                size_t idx = (size_t)m * DMODEL + n;
                float2 o;
                o.x = acc[mt][nt][h * 2 + 0] + bo[n] + resid[idx];
                o.y = acc[mt][nt][h * 2 + 1] + bo[n + 1] + resid[idx + 1];
                *(float2*)&outp[idx] = o;
            }
}

// ---------------- flash attention (bf16 HMMA, BM=128, BN=128, 256 thr) ---------
// 8 warps; warp owns 16 q-rows. K/V double-buffered. Each K/V tile serves
// 128 q-rows (halved smem-load traffic per output vs BM=64).
// Dynamic smem: Qs 16KB + Ks[2] 32KB + Vs[2] 32KB = 80KB.
#define ATTN_SMEM (128 * 64 * 2 + 4 * 128 * 64 * 2)
__global__ __launch_bounds__(256) void attn_kernel(const int* __restrict__ mask) {
    extern __shared__ bf16 smem_a[];
    bf16* Qs = smem_a;                       // 128 x 64
    bf16* Ks[2] = { Qs + 128 * 64, Qs + 128 * 64 + 128 * 64 };
    bf16* Vs[2] = { Qs + 3 * 128 * 64, Qs + 4 * 128 * 64 };

    int tid = threadIdx.x, lane = tid & 31, warp = tid >> 5;
    int qt = blockIdx.x, hh = blockIdx.y, bb = blockIdx.z;
    size_t headOff = (size_t)(bb * NHEAD + hh) * SEQ * HDIM;
    const bf16* qp = g_qb + headOff + (size_t)qt * 128 * HDIM;
    const bf16* kp = g_kb + headOff;
    const bf16* vp = g_vb + headOff;

    int lrow = tid >> 3, lc8 = tid & 7;   // lrow 0..31

#define KV_STAGE(st, ktile)                                                        \
    {                                                                              \
        const bf16* kt_p = kp + (size_t)(ktile) * 128 * HDIM;                      \
        const bf16* vt_p = vp + (size_t)(ktile) * 128 * HDIM;                      \
        _Pragma("unroll")                                                          \
        for (int p = 0; p < 4; p++) {                                              \
            int row = lrow + p * 32;                                               \
            cp16(s2u(Ks[st]) + sw128(row, lc8), kt_p + row * 64 + lc8 * 8);        \
            cp16(s2u(Vs[st]) + sw128(row, lc8), vt_p + row * 64 + lc8 * 8);        \
        }                                                                          \
    }

    // prologue: Q + stage 0
#pragma unroll
    for (int p = 0; p < 4; p++) {
        int row = lrow + p * 32;
        cp16(s2u(Qs) + sw128(row, lc8), qp + row * 64 + lc8 * 8);
    }
    KV_STAGE(0, 0);
    cp_commit(); cp_wait0();
    __syncthreads();

    int j = lane >> 3, l7 = lane & 7;
    uint32_t qf[4][4];
#pragma unroll
    for (int kt = 0; kt < 4; kt++) {
        int row = warp * 16 + ((j & 1) << 3) + l7;
        ldsm4(qf[kt], s2u(Qs) + sw128(row, kt * 2 + (j >> 1)));
    }

    float oacc[8][4];
#pragma unroll
    for (int nt = 0; nt < 8; nt++)
#pragma unroll
        for (int r = 0; r < 4; r++) oacc[nt][r] = 0.f;
    float m0 = -1e30f, m1 = -1e30f, l0 = 0.f, l1 = 0.f;
    bool use_mask = (g_mask_allones == 0);
    const float SC = 0.125f;   // 1/sqrt(64)

#pragma unroll 1
    for (int kt = 0; kt < SEQ / 128; kt++) {
        int st = kt & 1;
        if (kt < SEQ / 128 - 1) { KV_STAGE(st ^ 1, kt + 1); cp_commit(); }

        // --- scores = Q @ K^T over 128 kv cols ---
        float sacc[16][4];
#pragma unroll
        for (int nt = 0; nt < 16; nt++)
#pragma unroll
            for (int r = 0; r < 4; r++) sacc[nt][r] = 0.f;
        uint32_t kbse = s2u(Ks[st]);
#pragma unroll
        for (int kk = 0; kk < 4; kk++) {
#pragma unroll
            for (int np = 0; np < 8; np++) {
                int row = np * 16 + ((j >> 1) << 3) + l7;
                uint32_t r[4];
                ldsm4(r, kbse + sw128(row, kk * 2 + (j & 1)));
                uint32_t b0[2] = { r[0], r[1] };
                uint32_t b1[2] = { r[2], r[3] };
                mma16816(sacc[2 * np], qf[kk], b0);
                mma16816(sacc[2 * np + 1], qf[kk], b1);
            }
        }

        if (use_mask) {
            int r0g = qt * 128 + warp * 16 + (lane >> 2);
            const int* mr0 = mask + ((size_t)bb * SEQ + r0g) * SEQ + kt * 128;
            const int* mr1 = mr0 + 8 * SEQ;
#pragma unroll
            for (int nt = 0; nt < 16; nt++) {
                int c0 = nt * 8 + (lane & 3) * 2;
                if (mr0[c0] == 0)     sacc[nt][0] = -1e30f;
                if (mr0[c0 + 1] == 0) sacc[nt][1] = -1e30f;
                if (mr1[c0] == 0)     sacc[nt][2] = -1e30f;
                if (mr1[c0 + 1] == 0) sacc[nt][3] = -1e30f;
            }
        }

        // --- register online softmax (rows r0 = lane/4, r1 = r0+8) ---
        float mx0 = -1e30f, mx1 = -1e30f;
#pragma unroll
        for (int nt = 0; nt < 16; nt++) {
            mx0 = fmaxf(mx0, fmaxf(sacc[nt][0], sacc[nt][1]));
            mx1 = fmaxf(mx1, fmaxf(sacc[nt][2], sacc[nt][3]));
        }
        mx0 = fmaxf(mx0, __shfl_xor_sync(0xffffffffu, mx0, 1));
        mx0 = fmaxf(mx0, __shfl_xor_sync(0xffffffffu, mx0, 2));
        mx1 = fmaxf(mx1, __shfl_xor_sync(0xffffffffu, mx1, 1));
        mx1 = fmaxf(mx1, __shfl_xor_sync(0xffffffffu, mx1, 2));
        float mn0 = fmaxf(m0, mx0 * SC), mn1 = fmaxf(m1, mx1 * SC);
        float cr0 = __expf(m0 - mn0), cr1 = __expf(m1 - mn1);
        float ls0 = 0.f, ls1 = 0.f;
#pragma unroll
        for (int nt = 0; nt < 16; nt++) {
            sacc[nt][0] = __expf(fmaf(sacc[nt][0], SC, -mn0)); ls0 += sacc[nt][0];
            sacc[nt][1] = __expf(fmaf(sacc[nt][1], SC, -mn0)); ls0 += sacc[nt][1];
            sacc[nt][2] = __expf(fmaf(sacc[nt][2], SC, -mn1)); ls1 += sacc[nt][2];
            sacc[nt][3] = __expf(fmaf(sacc[nt][3], SC, -mn1)); ls1 += sacc[nt][3];
        }
        ls0 += __shfl_xor_sync(0xffffffffu, ls0, 1);
        ls0 += __shfl_xor_sync(0xffffffffu, ls0, 2);
        ls1 += __shfl_xor_sync(0xffffffffu, ls1, 1);
        ls1 += __shfl_xor_sync(0xffffffffu, ls1, 2);
        l0 = l0 * cr0 + ls0; m0 = mn0;
        l1 = l1 * cr1 + ls1; m1 = mn1;
#pragma unroll
        for (int nt = 0; nt < 8; nt++) {
            oacc[nt][0] *= cr0; oacc[nt][1] *= cr0;
            oacc[nt][2] *= cr1; oacc[nt][3] *= cr1;
        }

        // --- PV: oacc += P @ V over 128 kv rows ---
        uint32_t vbse = s2u(Vs[st]);
#pragma unroll
        for (int k2 = 0; k2 < 8; k2++) {
            uint32_t pa[4] = {
                pack_bf2(sacc[2 * k2][0],     sacc[2 * k2][1]),
                pack_bf2(sacc[2 * k2][2],     sacc[2 * k2][3]),
                pack_bf2(sacc[2 * k2 + 1][0], sacc[2 * k2 + 1][1]),
                pack_bf2(sacc[2 * k2 + 1][2], sacc[2 * k2 + 1][3])
            };
#pragma unroll
            for (int np = 0; np < 4; np++) {
                int row = k2 * 16 + ((j & 1) << 3) + l7;
                uint32_t r[4];
                ldsm4t(r, vbse + sw128(row, np * 2 + (j >> 1)));
                uint32_t b0[2] = { r[0], r[1] };
                uint32_t b1[2] = { r[2], r[3] };
                mma16816(oacc[2 * np], pa, b0);
                mma16816(oacc[2 * np + 1], pa, b1);
            }
        }

        if (kt < SEQ / 128 - 1) { cp_wait0(); __syncthreads(); }
    }
#undef KV_STAGE

    // --- epilogue: normalize + write bf16 [B*S, D] ---
    float inv0 = 1.f / l0, inv1 = 1.f / l1;
    int r4 = lane >> 2, c2 = (lane & 3) * 2;
    int s0 = qt * 128 + warp * 16 + r4;
#pragma unroll
    for (int nt = 0; nt < 8; nt++) {
        int d = nt * 8 + c2;
        *(uint32_t*)&g_attnb[(size_t)(bb * SEQ + s0) * DMODEL + hh * 64 + d] =
            pack_bf2(oacc[nt][0] * inv0, oacc[nt][1] * inv0);
        *(uint32_t*)&g_attnb[(size_t)(bb * SEQ + s0 + 8) * DMODEL + hh * 64 + d] =
            pack_bf2(oacc[nt][2] * inv1, oacc[nt][3] * inv1);
    }
}

// ---------------- launcher ------------------------------------------------------
extern "C" void kernel_launch(void* const* d_in, const int* in_sizes, int n_in,
                              void* d_out, int out_size) {
    const float* x     = (const float*)d_in[0];
    const int*   mask  = (const int*)d_in[1];
    const float* bq    = (const float*)d_in[3];
    const float* bk    = (const float*)d_in[5];
    const float* bv    = (const float*)d_in[7];
    const float* bo    = (const float*)d_in[9];
    const float* gamma = (const float*)d_in[10];
    const float* beta  = (const float*)d_in[11];
    float* outp = (float*)d_out;

    cudaFuncSetAttribute(attn_kernel, cudaFuncAttributeMaxDynamicSharedMemorySize,
                         ATTN_SMEM);

    ln_kernel<<<MROWS, 256>>>(x, gamma, beta);
    cvt_w_kernel<<<dim3(DMODEL * DMODEL / 1024, 4), 256>>>(
        (const float*)d_in[2], (const float*)d_in[4],
        (const float*)d_in[6], (const float*)d_in[8]);

    mask_scan_kernel<<<BATCH * SEQ * SEQ / 4 / (256 * 8), 256>>>((const int4*)mask);

    gemm_qkv<<<dim3(DMODEL / 128, MROWS / 128, 3), 256>>>(bq, bk, bv);

    attn_kernel<<<dim3(SEQ / 128, NHEAD, BATCH), 256, ATTN_SMEM>>>(mask);

    gemm_out<<<dim3(DMODEL / 128, MROWS / 128), 256>>>(bo, x, outp);
}

// round 11
// speedup vs baseline: 1.1832x; 1.1832x over previous
#include <cuda_runtime.h>
#include <cuda_bf16.h>
#include <cstdint>

#define BATCH 2
#define SEQ   2048
#define DMODEL 1024
#define NHEAD 16
#define HDIM  64
#define MROWS (BATCH * SEQ)
#define LN_EPS 1e-5f

typedef __nv_bfloat16 bf16;

// ---------------- device-global scratch (referenced ONLY from device code) ---
__device__ bf16 g_hb[(size_t)MROWS * DMODEL];
__device__ bf16 g_Wqb[DMODEL * DMODEL];
__device__ bf16 g_Wkb[DMODEL * DMODEL];
__device__ bf16 g_Wvb[DMODEL * DMODEL];
__device__ bf16 g_Wob[DMODEL * DMODEL];
__device__ bf16 g_qb[(size_t)MROWS * DMODEL];     // [B,H,S,hd]
__device__ bf16 g_kb[(size_t)MROWS * DMODEL];
__device__ bf16 g_vb[(size_t)MROWS * DMODEL];
__device__ bf16 g_attnb[(size_t)MROWS * DMODEL];  // [B*S, D]
__device__ int  g_mask_allones;

// ---------------- PTX helpers -------------------------------------------------
__device__ __forceinline__ uint32_t s2u(const void* p) {
    return (uint32_t)__cvta_generic_to_shared(p);
}
__device__ __forceinline__ void cp16(uint32_t saddr, const void* g) {
    asm volatile("cp.async.cg.shared.global [%0], [%1], 16;\n" :: "r"(saddr), "l"(g));
}
__device__ __forceinline__ void cp_commit() { asm volatile("cp.async.commit_group;\n"); }
__device__ __forceinline__ void cp_wait0()  { asm volatile("cp.async.wait_group 0;\n"); }

__device__ __forceinline__ void ldsm4(uint32_t r[4], uint32_t addr) {
    asm volatile("ldmatrix.sync.aligned.m8n8.x4.shared.b16 {%0,%1,%2,%3}, [%4];\n"
                 : "=r"(r[0]), "=r"(r[1]), "=r"(r[2]), "=r"(r[3]) : "r"(addr));
}
__device__ __forceinline__ void ldsm4t(uint32_t r[4], uint32_t addr) {
    asm volatile("ldmatrix.sync.aligned.m8n8.x4.trans.shared.b16 {%0,%1,%2,%3}, [%4];\n"
                 : "=r"(r[0]), "=r"(r[1]), "=r"(r[2]), "=r"(r[3]) : "r"(addr));
}
__device__ __forceinline__ void mma16816(float c[4], const uint32_t a[4], const uint32_t b[2]) {
    asm volatile(
        "mma.sync.aligned.m16n8k16.row.col.f32.bf16.bf16.f32 "
        "{%0,%1,%2,%3}, {%4,%5,%6,%7}, {%8,%9}, {%0,%1,%2,%3};\n"
        : "+f"(c[0]), "+f"(c[1]), "+f"(c[2]), "+f"(c[3])
        : "r"(a[0]), "r"(a[1]), "r"(a[2]), "r"(a[3]), "r"(b[0]), "r"(b[1]));
}
__device__ __forceinline__ uint32_t pack_bf2(float lo, float hi) {
    __nv_bfloat162 h = __floats2bfloat162_rn(lo, hi);
    return *reinterpret_cast<uint32_t*>(&h);
}
__device__ __forceinline__ int sw64(int row, int c16)  { return (row << 6) + ((c16 ^ ((row >> 1) & 3)) << 4); }
__device__ __forceinline__ int sw128(int row, int c16) { return (row << 7) + ((c16 ^ (row & 7)) << 4); }

// ---------------- layernorm -> bf16 ------------------------------------------
__global__ __launch_bounds__(256) void ln_kernel(const float* __restrict__ x,
                                                 const float* __restrict__ gamma,
                                                 const float* __restrict__ beta) {
    int row = blockIdx.x;
    const float* xr = x + (size_t)row * DMODEL;
    int c0 = threadIdx.x * 4;
    float4 f = *(const float4*)(xr + c0);
    float s  = f.x + f.y + f.z + f.w;
    float sq = f.x * f.x + f.y * f.y + f.z * f.z + f.w * f.w;
#pragma unroll
    for (int o = 16; o; o >>= 1) {
        s  += __shfl_xor_sync(0xffffffffu, s, o);
        sq += __shfl_xor_sync(0xffffffffu, sq, o);
    }
    __shared__ float ss[8], ssq[8];
    int w = threadIdx.x >> 5, l = threadIdx.x & 31;
    if (l == 0) { ss[w] = s; ssq[w] = sq; }
    __syncthreads();
    if (w == 0) {
        s  = (l < 8) ? ss[l]  : 0.f;
        sq = (l < 8) ? ssq[l] : 0.f;
#pragma unroll
        for (int o = 4; o; o >>= 1) {
            s  += __shfl_xor_sync(0xffffffffu, s, o);
            sq += __shfl_xor_sync(0xffffffffu, sq, o);
        }
        if (l == 0) { ss[0] = s; ssq[0] = sq; }
    }
    __syncthreads();
    float mu  = ss[0] * (1.f / DMODEL);
    float var = ssq[0] * (1.f / DMODEL) - mu * mu;
    float inv = rsqrtf(var + LN_EPS);
    float4 g = *(const float4*)(gamma + c0);
    float4 b = *(const float4*)(beta + c0);
    uint2 o;
    o.x = pack_bf2((f.x - mu) * inv * g.x + b.x, (f.y - mu) * inv * g.y + b.y);
    o.y = pack_bf2((f.z - mu) * inv * g.z + b.z, (f.w - mu) * inv * g.w + b.w);
    *(uint2*)&g_hb[(size_t)row * DMODEL + c0] = o;
}

// ---------------- weight fp32 -> bf16 (+ mask flag init) -----------------------
__global__ __launch_bounds__(256) void cvt_w_kernel(const float* __restrict__ Wq,
                                                    const float* __restrict__ Wk,
                                                    const float* __restrict__ Wv,
                                                    const float* __restrict__ Wo) {
    if (blockIdx.x == 0 && blockIdx.y == 0 && threadIdx.x == 0) g_mask_allones = 1;
    const float* src; bf16* dst;
    if (blockIdx.y == 0)      { src = Wq; dst = g_Wqb; }
    else if (blockIdx.y == 1) { src = Wk; dst = g_Wkb; }
    else if (blockIdx.y == 2) { src = Wv; dst = g_Wvb; }
    else                      { src = Wo; dst = g_Wob; }
    int i = (blockIdx.x * 256 + threadIdx.x) * 4;
    float4 f = *(const float4*)(src + i);
    uint2 o;
    o.x = pack_bf2(f.x, f.y);
    o.y = pack_bf2(f.z, f.w);
    *(uint2*)&dst[i] = o;
}

// ---------------- mask all-ones scan ------------------------------------------
__global__ __launch_bounds__(256) void mask_scan_kernel(const int4* __restrict__ m4) {
    int base = blockIdx.x * (256 * 8) + threadIdx.x;
    int4 t[8];
#pragma unroll
    for (int u = 0; u < 8; u++) t[u] = m4[base + u * 256];
    int ok = 1;
#pragma unroll
    for (int u = 0; u < 8; u++)
        ok &= (t[u].x != 0) & (t[u].y != 0) & (t[u].z != 0) & (t[u].w != 0);
    if (!ok) atomicAnd(&g_mask_allones, 0);
}

// ---------------- GEMM mainloop: 4 warps, warp tile 64x64, 2-stage cp.async ----
// CTA tile 128x128, BK=32. ldsm bytes/FLOP = 0.5 (vs 0.75 at 64x32 warp tile).
__device__ __forceinline__ void gemm_ml(const bf16* __restrict__ A,
                                        const bf16* __restrict__ W,
                                        int rowBase, int colBase,
                                        bf16 (*As)[128 * 32], bf16 (*Bs)[128 * 32],
                                        float acc[4][8][4]) {
    int tid = threadIdx.x, lane = tid & 31, warp = tid >> 5;
    int wm = warp >> 1, wn = warp & 1;
    int lrow = tid >> 2, lc = tid & 3;        // lrow 0..31, lc 0..3
    int j = lane >> 3, l7 = lane & 7;

#define GEMM_STAGE(st, kb)                                                         \
    {                                                                              \
        _Pragma("unroll")                                                          \
        for (int p = 0; p < 4; p++) {                                              \
            int row = lrow + p * 32;                                               \
            cp16(s2u(As[st]) + sw64(row, lc),                                      \
                 A + (size_t)(rowBase + row) * DMODEL + (kb) * 32 + lc * 8);       \
            cp16(s2u(Bs[st]) + sw64(row, lc),                                      \
                 W + (size_t)(colBase + row) * DMODEL + (kb) * 32 + lc * 8);       \
        }                                                                          \
    }

    GEMM_STAGE(0, 0);
    cp_commit(); cp_wait0();
    __syncthreads();

#pragma unroll 1
    for (int kb = 0; kb < 32; kb++) {
        int st = kb & 1;
        if (kb < 31) { GEMM_STAGE(st ^ 1, kb + 1); cp_commit(); }
        uint32_t ab = s2u(As[st]), bb_ = s2u(Bs[st]);
#pragma unroll
        for (int kt = 0; kt < 2; kt++) {
            uint32_t a[4][4];
#pragma unroll
            for (int mt = 0; mt < 4; mt++) {
                int row = wm * 64 + mt * 16 + ((j & 1) << 3) + l7;
                ldsm4(a[mt], ab + sw64(row, kt * 2 + (j >> 1)));
            }
            uint32_t b[8][2];
#pragma unroll
            for (int np = 0; np < 4; np++) {
                int row = wn * 64 + np * 16 + ((j >> 1) << 3) + l7;
                uint32_t r[4];
                ldsm4(r, bb_ + sw64(row, kt * 2 + (j & 1)));
                b[2 * np][0] = r[0]; b[2 * np][1] = r[1];
                b[2 * np + 1][0] = r[2]; b[2 * np + 1][1] = r[3];
            }
#pragma unroll
            for (int mt = 0; mt < 4; mt++)
#pragma unroll
                for (int nt = 0; nt < 8; nt++)
                    mma16816(acc[mt][nt], a[mt], b[nt]);
        }
        if (kb < 31) { cp_wait0(); __syncthreads(); }
    }
#undef GEMM_STAGE
}

// ---------------- QKV GEMM: bf16 out reordered to [B,H,S,hd] -------------------
__global__ __launch_bounds__(128, 2) void gemm_qkv(const float* __restrict__ bq,
                                                   const float* __restrict__ bk,
                                                   const float* __restrict__ bv) {
    __shared__ bf16 As[2][128 * 32], Bs[2][128 * 32];
    const bf16* W; const float* bias; bf16* C;
    if (blockIdx.z == 0)      { W = g_Wqb; bias = bq; C = g_qb; }
    else if (blockIdx.z == 1) { W = g_Wkb; bias = bk; C = g_kb; }
    else                      { W = g_Wvb; bias = bv; C = g_vb; }

    float acc[4][8][4];
#pragma unroll
    for (int i = 0; i < 4; i++)
#pragma unroll
        for (int k = 0; k < 8; k++)
#pragma unroll
            for (int r = 0; r < 4; r++) acc[i][k][r] = 0.f;

    int rowBase = blockIdx.y * 128, colBase = blockIdx.x * 128;
    gemm_ml(g_hb, W, rowBase, colBase, As, Bs, acc);

    int lane = threadIdx.x & 31, warp = threadIdx.x >> 5;
    int wm = warp >> 1, wn = warp & 1;
    int r4 = lane >> 2, c2 = (lane & 3) * 2;
#pragma unroll
    for (int mt = 0; mt < 4; mt++)
#pragma unroll
        for (int nt = 0; nt < 8; nt++)
#pragma unroll
            for (int h = 0; h < 2; h++) {
                int m = rowBase + wm * 64 + mt * 16 + r4 + h * 8;
                int n = colBase + wn * 64 + nt * 8 + c2;
                float v0 = acc[mt][nt][h * 2 + 0] + bias[n];
                float v1 = acc[mt][nt][h * 2 + 1] + bias[n + 1];
                int bbi = m >> 11, s = m & 2047, hh = n >> 6, d = n & 63;
                *(uint32_t*)&C[(((size_t)(bbi * NHEAD + hh) * SEQ + s) << 6) + d] =
                    pack_bf2(v0, v1);
            }
}

// ---------------- out GEMM: fp32 out = attn @ Wo^T + bo + residual -------------
__global__ __launch_bounds__(128, 2) void gemm_out(const float* __restrict__ bo,
                                                   const float* __restrict__ resid,
                                                   float* __restrict__ outp) {
    __shared__ bf16 As[2][128 * 32], Bs[2][128 * 32];
    float acc[4][8][4];
#pragma unroll
    for (int i = 0; i < 4; i++)
#pragma unroll
        for (int k = 0; k < 8; k++)
#pragma unroll
            for (int r = 0; r < 4; r++) acc[i][k][r] = 0.f;

    int rowBase = blockIdx.y * 128, colBase = blockIdx.x * 128;
    gemm_ml(g_attnb, g_Wob, rowBase, colBase, As, Bs, acc);

    int lane = threadIdx.x & 31, warp = threadIdx.x >> 5;
    int wm = warp >> 1, wn = warp & 1;
    int r4 = lane >> 2, c2 = (lane & 3) * 2;
#pragma unroll
    for (int mt = 0; mt < 4; mt++)
#pragma unroll
        for (int nt = 0; nt < 8; nt++)
#pragma unroll
            for (int h = 0; h < 2; h++) {
                int m = rowBase + wm * 64 + mt * 16 + r4 + h * 8;
                int n = colBase + wn * 64 + nt * 8 + c2;
                size_t idx = (size_t)m * DMODEL + n;
                float2 o;
                o.x = acc[mt][nt][h * 2 + 0] + bo[n] + resid[idx];
                o.y = acc[mt][nt][h * 2 + 1] + bo[n + 1] + resid[idx + 1];
                *(float2*)&outp[idx] = o;
            }
}

// ---------------- flash attention (R6 config: BM=64, BN=128, 128 thr) ----------
// 4 warps; warp owns 16 q-rows. K/V double-buffered. 72KB dynamic smem.
#define ATTN_SMEM (64 * 64 * 2 + 4 * 128 * 64 * 2)
__global__ __launch_bounds__(128) void attn_kernel(const int* __restrict__ mask) {
    extern __shared__ bf16 smem_a[];
    bf16* Qs = smem_a;                       // 64 x 64
    bf16* Ks[2] = { Qs + 64 * 64, Qs + 64 * 64 + 128 * 64 };
    bf16* Vs[2] = { Qs + 64 * 64 + 2 * 128 * 64, Qs + 64 * 64 + 3 * 128 * 64 };

    int tid = threadIdx.x, lane = tid & 31, warp = tid >> 5;
    int qt = blockIdx.x, hh = blockIdx.y, bb = blockIdx.z;
    size_t headOff = (size_t)(bb * NHEAD + hh) * SEQ * HDIM;
    const bf16* qp = g_qb + headOff + (size_t)qt * 64 * HDIM;
    const bf16* kp = g_kb + headOff;
    const bf16* vp = g_vb + headOff;

    int lrow = tid >> 3, lc8 = tid & 7;   // lrow 0..15

#define KV_STAGE(st, ktile)                                                        \
    {                                                                              \
        const bf16* kt_p = kp + (size_t)(ktile) * 128 * HDIM;                      \
        const bf16* vt_p = vp + (size_t)(ktile) * 128 * HDIM;                      \
        _Pragma("unroll")                                                          \
        for (int p = 0; p < 8; p++) {                                              \
            int row = lrow + p * 16;                                               \
            cp16(s2u(Ks[st]) + sw128(row, lc8), kt_p + row * 64 + lc8 * 8);        \
            cp16(s2u(Vs[st]) + sw128(row, lc8), vt_p + row * 64 + lc8 * 8);        \
        }                                                                          \
    }

    // prologue: Q + stage 0
#pragma unroll
    for (int p = 0; p < 4; p++) {
        int row = lrow + p * 16;
        cp16(s2u(Qs) + sw128(row, lc8), qp + row * 64 + lc8 * 8);
    }
    KV_STAGE(0, 0);
    cp_commit(); cp_wait0();
    __syncthreads();

    int j = lane >> 3, l7 = lane & 7;
    uint32_t qf[4][4];
#pragma unroll
    for (int kt = 0; kt < 4; kt++) {
        int row = warp * 16 + ((j & 1) << 3) + l7;
        ldsm4(qf[kt], s2u(Qs) + sw128(row, kt * 2 + (j >> 1)));
    }

    float oacc[8][4];
#pragma unroll
    for (int nt = 0; nt < 8; nt++)
#pragma unroll
        for (int r = 0; r < 4; r++) oacc[nt][r] = 0.f;
    float m0 = -1e30f, m1 = -1e30f, l0 = 0.f, l1 = 0.f;
    bool use_mask = (g_mask_allones == 0);
    const float SC = 0.125f;   // 1/sqrt(64)

#pragma unroll 1
    for (int kt = 0; kt < SEQ / 128; kt++) {
        int st = kt & 1;
        if (kt < SEQ / 128 - 1) { KV_STAGE(st ^ 1, kt + 1); cp_commit(); }

        // --- scores = Q @ K^T over 128 kv cols ---
        float sacc[16][4];
#pragma unroll
        for (int nt = 0; nt < 16; nt++)
#pragma unroll
            for (int r = 0; r < 4; r++) sacc[nt][r] = 0.f;
        uint32_t kbse = s2u(Ks[st]);
#pragma unroll
        for (int kk = 0; kk < 4; kk++) {
#pragma unroll
            for (int np = 0; np < 8; np++) {
                int row = np * 16 + ((j >> 1) << 3) + l7;
                uint32_t r[4];
                ldsm4(r, kbse + sw128(row, kk * 2 + (j & 1)));
                uint32_t b0[2] = { r[0], r[1] };
                uint32_t b1[2] = { r[2], r[3] };
                mma16816(sacc[2 * np], qf[kk], b0);
                mma16816(sacc[2 * np + 1], qf[kk], b1);
            }
        }

        if (use_mask) {
            int r0g = qt * 64 + warp * 16 + (lane >> 2);
            const int* mr0 = mask + ((size_t)bb * SEQ + r0g) * SEQ + kt * 128;
            const int* mr1 = mr0 + 8 * SEQ;
#pragma unroll
            for (int nt = 0; nt < 16; nt++) {
                int c0 = nt * 8 + (lane & 3) * 2;
                if (mr0[c0] == 0)     sacc[nt][0] = -1e30f;
                if (mr0[c0 + 1] == 0) sacc[nt][1] = -1e30f;
                if (mr1[c0] == 0)     sacc[nt][2] = -1e30f;
                if (mr1[c0 + 1] == 0) sacc[nt][3] = -1e30f;
            }
        }

        // --- register online softmax (rows r0 = lane/4, r1 = r0+8) ---
        float mx0 = -1e30f, mx1 = -1e30f;
#pragma unroll
        for (int nt = 0; nt < 16; nt++) {
            mx0 = fmaxf(mx0, fmaxf(sacc[nt][0], sacc[nt][1]));
            mx1 = fmaxf(mx1, fmaxf(sacc[nt][2], sacc[nt][3]));
        }
        mx0 = fmaxf(mx0, __shfl_xor_sync(0xffffffffu, mx0, 1));
        mx0 = fmaxf(mx0, __shfl_xor_sync(0xffffffffu, mx0, 2));
        mx1 = fmaxf(mx1, __shfl_xor_sync(0xffffffffu, mx1, 1));
        mx1 = fmaxf(mx1, __shfl_xor_sync(0xffffffffu, mx1, 2));
        float mn0 = fmaxf(m0, mx0 * SC), mn1 = fmaxf(m1, mx1 * SC);
        float cr0 = __expf(m0 - mn0), cr1 = __expf(m1 - mn1);
        float ls0 = 0.f, ls1 = 0.f;
#pragma unroll
        for (int nt = 0; nt < 16; nt++) {
            sacc[nt][0] = __expf(fmaf(sacc[nt][0], SC, -mn0)); ls0 += sacc[nt][0];
            sacc[nt][1] = __expf(fmaf(sacc[nt][1], SC, -mn0)); ls0 += sacc[nt][1];
            sacc[nt][2] = __expf(fmaf(sacc[nt][2], SC, -mn1)); ls1 += sacc[nt][2];
            sacc[nt][3] = __expf(fmaf(sacc[nt][3], SC, -mn1)); ls1 += sacc[nt][3];
        }
        ls0 += __shfl_xor_sync(0xffffffffu, ls0, 1);
        ls0 += __shfl_xor_sync(0xffffffffu, ls0, 2);
        ls1 += __shfl_xor_sync(0xffffffffu, ls1, 1);
        ls1 += __shfl_xor_sync(0xffffffffu, ls1, 2);
        l0 = l0 * cr0 + ls0; m0 = mn0;
        l1 = l1 * cr1 + ls1; m1 = mn1;
#pragma unroll
        for (int nt = 0; nt < 8; nt++) {
            oacc[nt][0] *= cr0; oacc[nt][1] *= cr0;
            oacc[nt][2] *= cr1; oacc[nt][3] *= cr1;
        }

        // --- PV: oacc += P @ V over 128 kv rows ---
        uint32_t vbse = s2u(Vs[st]);
#pragma unroll
        for (int k2 = 0; k2 < 8; k2++) {
            uint32_t pa[4] = {
                pack_bf2(sacc[2 * k2][0],     sacc[2 * k2][1]),
                pack_bf2(sacc[2 * k2][2],     sacc[2 * k2][3]),
                pack_bf2(sacc[2 * k2 + 1][0], sacc[2 * k2 + 1][1]),
                pack_bf2(sacc[2 * k2 + 1][2], sacc[2 * k2 + 1][3])
            };
#pragma unroll
            for (int np = 0; np < 4; np++) {
                int row = k2 * 16 + ((j & 1) << 3) + l7;
                uint32_t r[4];
                ldsm4t(r, vbse + sw128(row, np * 2 + (j >> 1)));
                uint32_t b0[2] = { r[0], r[1] };
                uint32_t b1[2] = { r[2], r[3] };
                mma16816(oacc[2 * np], pa, b0);
                mma16816(oacc[2 * np + 1], pa, b1);
            }
        }

        if (kt < SEQ / 128 - 1) { cp_wait0(); __syncthreads(); }
    }
#undef KV_STAGE

    // --- epilogue: normalize + write bf16 [B*S, D] ---
    float inv0 = 1.f / l0, inv1 = 1.f / l1;
    int r4 = lane >> 2, c2 = (lane & 3) * 2;
    int s0 = qt * 64 + warp * 16 + r4;
#pragma unroll
    for (int nt = 0; nt < 8; nt++) {
        int d = nt * 8 + c2;
        *(uint32_t*)&g_attnb[(size_t)(bb * SEQ + s0) * DMODEL + hh * 64 + d] =
            pack_bf2(oacc[nt][0] * inv0, oacc[nt][1] * inv0);
        *(uint32_t*)&g_attnb[(size_t)(bb * SEQ + s0 + 8) * DMODEL + hh * 64 + d] =
            pack_bf2(oacc[nt][2] * inv1, oacc[nt][3] * inv1);
    }
}

// ---------------- launcher ------------------------------------------------------
extern "C" void kernel_launch(void* const* d_in, const int* in_sizes, int n_in,
                              void* d_out, int out_size) {
    const float* x     = (const float*)d_in[0];
    const int*   mask  = (const int*)d_in[1];
    const float* bq    = (const float*)d_in[3];
    const float* bk    = (const float*)d_in[5];
    const float* bv    = (const float*)d_in[7];
    const float* bo    = (const float*)d_in[9];
    const float* gamma = (const float*)d_in[10];
    const float* beta  = (const float*)d_in[11];
    float* outp = (float*)d_out;

    cudaFuncSetAttribute(attn_kernel, cudaFuncAttributeMaxDynamicSharedMemorySize,
                         ATTN_SMEM);

    ln_kernel<<<MROWS, 256>>>(x, gamma, beta);
    cvt_w_kernel<<<dim3(DMODEL * DMODEL / 1024, 4), 256>>>(
        (const float*)d_in[2], (const float*)d_in[4],
        (const float*)d_in[6], (const float*)d_in[8]);

    mask_scan_kernel<<<BATCH * SEQ * SEQ / 4 / (256 * 8), 256>>>((const int4*)mask);

    gemm_qkv<<<dim3(DMODEL / 128, MROWS / 128, 3), 128>>>(bq, bk, bv);

    attn_kernel<<<dim3(SEQ / 64, NHEAD, BATCH), 128, ATTN_SMEM>>>(mask);

    gemm_out<<<dim3(DMODEL / 128, MROWS / 128), 128>>>(bo, x, outp);
}

// round 13
// speedup vs baseline: 1.2753x; 1.0778x over previous
#include <cuda_runtime.h>
#include <cuda_bf16.h>
#include <cstdint>

#define BATCH 2
#define SEQ   2048
#define DMODEL 1024
#define NHEAD 16
#define HDIM  64
#define MROWS (BATCH * SEQ)
#define LN_EPS 1e-5f

typedef __nv_bfloat16 bf16;

// ---------------- device-global scratch (referenced ONLY from device code) ---
__device__ bf16 g_hb[(size_t)MROWS * DMODEL];
__device__ bf16 g_Wqb[DMODEL * DMODEL];
__device__ bf16 g_Wkb[DMODEL * DMODEL];
__device__ bf16 g_Wvb[DMODEL * DMODEL];
__device__ bf16 g_Wob[DMODEL * DMODEL];
__device__ bf16 g_qb[(size_t)MROWS * DMODEL];     // [B,H,S,hd]
__device__ bf16 g_kb[(size_t)MROWS * DMODEL];
__device__ bf16 g_vb[(size_t)MROWS * DMODEL];
__device__ bf16 g_attnb[(size_t)MROWS * DMODEL];  // [B*S, D]
__device__ int  g_mask_allones;

// ---------------- PTX helpers -------------------------------------------------
__device__ __forceinline__ uint32_t s2u(const void* p) {
    return (uint32_t)__cvta_generic_to_shared(p);
}
__device__ __forceinline__ void cp16(uint32_t saddr, const void* g) {
    asm volatile("cp.async.cg.shared.global [%0], [%1], 16;\n" :: "r"(saddr), "l"(g));
}
__device__ __forceinline__ void cp_commit() { asm volatile("cp.async.commit_group;\n"); }
__device__ __forceinline__ void cp_wait0()  { asm volatile("cp.async.wait_group 0;\n"); }

__device__ __forceinline__ void ldsm4(uint32_t r[4], uint32_t addr) {
    asm volatile("ldmatrix.sync.aligned.m8n8.x4.shared.b16 {%0,%1,%2,%3}, [%4];\n"
                 : "=r"(r[0]), "=r"(r[1]), "=r"(r[2]), "=r"(r[3]) : "r"(addr));
}
__device__ __forceinline__ void ldsm4t(uint32_t r[4], uint32_t addr) {
    asm volatile("ldmatrix.sync.aligned.m8n8.x4.trans.shared.b16 {%0,%1,%2,%3}, [%4];\n"
                 : "=r"(r[0]), "=r"(r[1]), "=r"(r[2]), "=r"(r[3]) : "r"(addr));
}
__device__ __forceinline__ void mma16816(float c[4], const uint32_t a[4], const uint32_t b[2]) {
    asm volatile(
        "mma.sync.aligned.m16n8k16.row.col.f32.bf16.bf16.f32 "
        "{%0,%1,%2,%3}, {%4,%5,%6,%7}, {%8,%9}, {%0,%1,%2,%3};\n"
        : "+f"(c[0]), "+f"(c[1]), "+f"(c[2]), "+f"(c[3])
        : "r"(a[0]), "r"(a[1]), "r"(a[2]), "r"(a[3]), "r"(b[0]), "r"(b[1]));
}
__device__ __forceinline__ uint32_t pack_bf2(float lo, float hi) {
    __nv_bfloat162 h = __floats2bfloat162_rn(lo, hi);
    return *reinterpret_cast<uint32_t*>(&h);
}
__device__ __forceinline__ float ex2f(float x) {
    float y;
    asm("ex2.approx.ftz.f32 %0, %1;" : "=f"(y) : "f"(x));
    return y;
}
__device__ __forceinline__ int sw64(int row, int c16)  { return (row << 6) + ((c16 ^ ((row >> 1) & 3)) << 4); }
__device__ __forceinline__ int sw128(int row, int c16) { return (row << 7) + ((c16 ^ (row & 7)) << 4); }

// ---------------- layernorm -> bf16 ------------------------------------------
__global__ __launch_bounds__(256) void ln_kernel(const float* __restrict__ x,
                                                 const float* __restrict__ gamma,
                                                 const float* __restrict__ beta) {
    int row = blockIdx.x;
    const float* xr = x + (size_t)row * DMODEL;
    int c0 = threadIdx.x * 4;
    float4 f = *(const float4*)(xr + c0);
    float s  = f.x + f.y + f.z + f.w;
    float sq = f.x * f.x + f.y * f.y + f.z * f.z + f.w * f.w;
#pragma unroll
    for (int o = 16; o; o >>= 1) {
        s  += __shfl_xor_sync(0xffffffffu, s, o);
        sq += __shfl_xor_sync(0xffffffffu, sq, o);
    }
    __shared__ float ss[8], ssq[8];
    int w = threadIdx.x >> 5, l = threadIdx.x & 31;
    if (l == 0) { ss[w] = s; ssq[w] = sq; }
    __syncthreads();
    if (w == 0) {
        s  = (l < 8) ? ss[l]  : 0.f;
        sq = (l < 8) ? ssq[l] : 0.f;
#pragma unroll
        for (int o = 4; o; o >>= 1) {
            s  += __shfl_xor_sync(0xffffffffu, s, o);
            sq += __shfl_xor_sync(0xffffffffu, sq, o);
        }
        if (l == 0) { ss[0] = s; ssq[0] = sq; }
    }
    __syncthreads();
    float mu  = ss[0] * (1.f / DMODEL);
    float var = ssq[0] * (1.f / DMODEL) - mu * mu;
    float inv = rsqrtf(var + LN_EPS);
    float4 g = *(const float4*)(gamma + c0);
    float4 b = *(const float4*)(beta + c0);
    uint2 o;
    o.x = pack_bf2((f.x - mu) * inv * g.x + b.x, (f.y - mu) * inv * g.y + b.y);
    o.y = pack_bf2((f.z - mu) * inv * g.z + b.z, (f.w - mu) * inv * g.w + b.w);
    *(uint2*)&g_hb[(size_t)row * DMODEL + c0] = o;
}

// ---------------- weight fp32 -> bf16 (+ mask flag init) -----------------------
__global__ __launch_bounds__(256) void cvt_w_kernel(const float* __restrict__ Wq,
                                                    const float* __restrict__ Wk,
                                                    const float* __restrict__ Wv,
                                                    const float* __restrict__ Wo) {
    if (blockIdx.x == 0 && blockIdx.y == 0 && threadIdx.x == 0) g_mask_allones = 1;
    const float* src; bf16* dst;
    if (blockIdx.y == 0)      { src = Wq; dst = g_Wqb; }
    else if (blockIdx.y == 1) { src = Wk; dst = g_Wkb; }
    else if (blockIdx.y == 2) { src = Wv; dst = g_Wvb; }
    else                      { src = Wo; dst = g_Wob; }
    int i = (blockIdx.x * 256 + threadIdx.x) * 4;
    float4 f = *(const float4*)(src + i);
    uint2 o;
    o.x = pack_bf2(f.x, f.y);
    o.y = pack_bf2(f.z, f.w);
    *(uint2*)&dst[i] = o;
}

// ---------------- mask all-ones scan ------------------------------------------
__global__ __launch_bounds__(256) void mask_scan_kernel(const int4* __restrict__ m4) {
    int base = blockIdx.x * (256 * 8) + threadIdx.x;
    int4 t[8];
#pragma unroll
    for (int u = 0; u < 8; u++) t[u] = m4[base + u * 256];
    int ok = 1;
#pragma unroll
    for (int u = 0; u < 8; u++)
        ok &= (t[u].x != 0) & (t[u].y != 0) & (t[u].z != 0) & (t[u].w != 0);
    if (!ok) atomicAnd(&g_mask_allones, 0);
}

// ---------------- GEMM mainloop: 4 warps, warp tile 64x64, 2-stage cp.async ----
// CTA tile 128x128, BK=32. (R11 measured winner: qkv 73.8us @ tensor 58%)
__device__ __forceinline__ void gemm_ml(const bf16* __restrict__ A,
                                        const bf16* __restrict__ W,
                                        int rowBase, int colBase,
                                        bf16 (*As)[128 * 32], bf16 (*Bs)[128 * 32],
                                        float acc[4][8][4]) {
    int tid = threadIdx.x, lane = tid & 31, warp = tid >> 5;
    int wm = warp >> 1, wn = warp & 1;
    int lrow = tid >> 2, lc = tid & 3;
    int j = lane >> 3, l7 = lane & 7;

#define GEMM_STAGE(st, kb)                                                         \
    {                                                                              \
        _Pragma("unroll")                                                          \
        for (int p = 0; p < 4; p++) {                                              \
            int row = lrow + p * 32;                                               \
            cp16(s2u(As[st]) + sw64(row, lc),                                      \
                 A + (size_t)(rowBase + row) * DMODEL + (kb) * 32 + lc * 8);       \
            cp16(s2u(Bs[st]) + sw64(row, lc),                                      \
                 W + (size_t)(colBase + row) * DMODEL + (kb) * 32 + lc * 8);       \
        }                                                                          \
    }

    GEMM_STAGE(0, 0);
    cp_commit(); cp_wait0();
    __syncthreads();

#pragma unroll 1
    for (int kb = 0; kb < 32; kb++) {
        int st = kb & 1;
        if (kb < 31) { GEMM_STAGE(st ^ 1, kb + 1); cp_commit(); }
        uint32_t ab = s2u(As[st]), bb_ = s2u(Bs[st]);
#pragma unroll
        for (int kt = 0; kt < 2; kt++) {
            uint32_t a[4][4];
#pragma unroll
            for (int mt = 0; mt < 4; mt++) {
                int row = wm * 64 + mt * 16 + ((j & 1) << 3) + l7;
                ldsm4(a[mt], ab + sw64(row, kt * 2 + (j >> 1)));
            }
            uint32_t b[8][2];
#pragma unroll
            for (int np = 0; np < 4; np++) {
                int row = wn * 64 + np * 16 + ((j >> 1) << 3) + l7;
                uint32_t r[4];
                ldsm4(r, bb_ + sw64(row, kt * 2 + (j & 1)));
                b[2 * np][0] = r[0]; b[2 * np][1] = r[1];
                b[2 * np + 1][0] = r[2]; b[2 * np + 1][1] = r[3];
            }
#pragma unroll
            for (int mt = 0; mt < 4; mt++)
#pragma unroll
                for (int nt = 0; nt < 8; nt++)
                    mma16816(acc[mt][nt], a[mt], b[nt]);
        }
        if (kb < 31) { cp_wait0(); __syncthreads(); }
    }
#undef GEMM_STAGE
}

// ---------------- QKV GEMM: bf16 out reordered to [B,H,S,hd] -------------------
__global__ __launch_bounds__(128, 2) void gemm_qkv(const float* __restrict__ bq,
                                                   const float* __restrict__ bk,
                                                   const float* __restrict__ bv) {
    __shared__ bf16 As[2][128 * 32], Bs[2][128 * 32];
    const bf16* W; const float* bias; bf16* C;
    if (blockIdx.z == 0)      { W = g_Wqb; bias = bq; C = g_qb; }
    else if (blockIdx.z == 1) { W = g_Wkb; bias = bk; C = g_kb; }
    else                      { W = g_Wvb; bias = bv; C = g_vb; }

    float acc[4][8][4];
#pragma unroll
    for (int i = 0; i < 4; i++)
#pragma unroll
        for (int k = 0; k < 8; k++)
#pragma unroll
            for (int r = 0; r < 4; r++) acc[i][k][r] = 0.f;

    int rowBase = blockIdx.y * 128, colBase = blockIdx.x * 128;
    gemm_ml(g_hb, W, rowBase, colBase, As, Bs, acc);

    int lane = threadIdx.x & 31, warp = threadIdx.x >> 5;
    int wm = warp >> 1, wn = warp & 1;
    int r4 = lane >> 2, c2 = (lane & 3) * 2;
#pragma unroll
    for (int mt = 0; mt < 4; mt++)
#pragma unroll
        for (int nt = 0; nt < 8; nt++)
#pragma unroll
            for (int h = 0; h < 2; h++) {
                int m = rowBase + wm * 64 + mt * 16 + r4 + h * 8;
                int n = colBase + wn * 64 + nt * 8 + c2;
                float v0 = acc[mt][nt][h * 2 + 0] + bias[n];
                float v1 = acc[mt][nt][h * 2 + 1] + bias[n + 1];
                int bbi = m >> 11, s = m & 2047, hh = n >> 6, d = n & 63;
                *(uint32_t*)&C[(((size_t)(bbi * NHEAD + hh) * SEQ + s) << 6) + d] =
                    pack_bf2(v0, v1);
            }
}

// ---------------- out GEMM: fp32 out = attn @ Wo^T + bo + residual -------------
__global__ __launch_bounds__(128, 2) void gemm_out(const float* __restrict__ bo,
                                                   const float* __restrict__ resid,
                                                   float* __restrict__ outp) {
    __shared__ bf16 As[2][128 * 32], Bs[2][128 * 32];
    float acc[4][8][4];
#pragma unroll
    for (int i = 0; i < 4; i++)
#pragma unroll
        for (int k = 0; k < 8; k++)
#pragma unroll
            for (int r = 0; r < 4; r++) acc[i][k][r] = 0.f;

    int rowBase = blockIdx.y * 128, colBase = blockIdx.x * 128;
    gemm_ml(g_attnb, g_Wob, rowBase, colBase, As, Bs, acc);

    int lane = threadIdx.x & 31, warp = threadIdx.x >> 5;
    int wm = warp >> 1, wn = warp & 1;
    int r4 = lane >> 2, c2 = (lane & 3) * 2;
#pragma unroll
    for (int mt = 0; mt < 4; mt++)
#pragma unroll
        for (int nt = 0; nt < 8; nt++)
#pragma unroll
            for (int h = 0; h < 2; h++) {
                int m = rowBase + wm * 64 + mt * 16 + r4 + h * 8;
                int n = colBase + wn * 64 + nt * 8 + c2;
                size_t idx = (size_t)m * DMODEL + n;
                float2 o;
                o.x = acc[mt][nt][h * 2 + 0] + bo[n] + resid[idx];
                o.y = acc[mt][nt][h * 2 + 1] + bo[n + 1] + resid[idx + 1];
                *(float2*)&outp[idx] = o;
            }
}

// ---------------- flash attention (BM=64, BN=128, 128 thr, 3 CTA/SM target) ----
// log2-domain online softmax: m/l tracked in base-2; single ex2 per element.
#define ATTN_SMEM (64 * 64 * 2 + 4 * 128 * 64 * 2)
__global__ __launch_bounds__(128, 3) void attn_kernel(const int* __restrict__ mask) {
    extern __shared__ bf16 smem_a[];
    bf16* Qs = smem_a;                       // 64 x 64
    bf16* Ks[2] = { Qs + 64 * 64, Qs + 64 * 64 + 128 * 64 };
    bf16* Vs[2] = { Qs + 64 * 64 + 2 * 128 * 64, Qs + 64 * 64 + 3 * 128 * 64 };

    int tid = threadIdx.x, lane = tid & 31, warp = tid >> 5;
    int qt = blockIdx.x, hh = blockIdx.y, bb = blockIdx.z;
    size_t headOff = (size_t)(bb * NHEAD + hh) * SEQ * HDIM;
    const bf16* qp = g_qb + headOff + (size_t)qt * 64 * HDIM;
    const bf16* kp = g_kb + headOff;
    const bf16* vp = g_vb + headOff;

    int lrow = tid >> 3, lc8 = tid & 7;

#define KV_STAGE(st, ktile)                                                        \
    {                                                                              \
        const bf16* kt_p = kp + (size_t)(ktile) * 128 * HDIM;                      \
        const bf16* vt_p = vp + (size_t)(ktile) * 128 * HDIM;                      \
        _Pragma("unroll")                                                          \
        for (int p = 0; p < 8; p++) {                                              \
            int row = lrow + p * 16;                                               \
            cp16(s2u(Ks[st]) + sw128(row, lc8), kt_p + row * 64 + lc8 * 8);        \
            cp16(s2u(Vs[st]) + sw128(row, lc8), vt_p + row * 64 + lc8 * 8);        \
        }                                                                          \
    }

#pragma unroll
    for (int p = 0; p < 4; p++) {
        int row = lrow + p * 16;
        cp16(s2u(Qs) + sw128(row, lc8), qp + row * 64 + lc8 * 8);
    }
    KV_STAGE(0, 0);
    cp_commit(); cp_wait0();
    __syncthreads();

    int j = lane >> 3, l7 = lane & 7;
    uint32_t qf[4][4];
#pragma unroll
    for (int kt = 0; kt < 4; kt++) {
        int row = warp * 16 + ((j & 1) << 3) + l7;
        ldsm4(qf[kt], s2u(Qs) + sw128(row, kt * 2 + (j >> 1)));
    }

    float oacc[8][4];
#pragma unroll
    for (int nt = 0; nt < 8; nt++)
#pragma unroll
        for (int r = 0; r < 4; r++) oacc[nt][r] = 0.f;
    float m0 = -1e30f, m1 = -1e30f, l0 = 0.f, l1 = 0.f;
    bool use_mask = (g_mask_allones == 0);
    const float SC2 = 0.125f * 1.44269504088896f;   // (1/sqrt(64)) * log2(e)

#pragma unroll 1
    for (int kt = 0; kt < SEQ / 128; kt++) {
        int st = kt & 1;
        if (kt < SEQ / 128 - 1) { KV_STAGE(st ^ 1, kt + 1); cp_commit(); }

        // --- scores = Q @ K^T over 128 kv cols ---
        float sacc[16][4];
#pragma unroll
        for (int nt = 0; nt < 16; nt++)
#pragma unroll
            for (int r = 0; r < 4; r++) sacc[nt][r] = 0.f;
        uint32_t kbse = s2u(Ks[st]);
#pragma unroll
        for (int kk = 0; kk < 4; kk++) {
#pragma unroll
            for (int np = 0; np < 8; np++) {
                int row = np * 16 + ((j >> 1) << 3) + l7;
                uint32_t r[4];
                ldsm4(r, kbse + sw128(row, kk * 2 + (j & 1)));
                uint32_t b0[2] = { r[0], r[1] };
                uint32_t b1[2] = { r[2], r[3] };
                mma16816(sacc[2 * np], qf[kk], b0);
                mma16816(sacc[2 * np + 1], qf[kk], b1);
            }
        }

        if (use_mask) {
            int r0g = qt * 64 + warp * 16 + (lane >> 2);
            const int* mr0 = mask + ((size_t)bb * SEQ + r0g) * SEQ + kt * 128;
            const int* mr1 = mr0 + 8 * SEQ;
#pragma unroll
            for (int nt = 0; nt < 16; nt++) {
                int c0 = nt * 8 + (lane & 3) * 2;
                if (mr0[c0] == 0)     sacc[nt][0] = -1e30f;
                if (mr0[c0 + 1] == 0) sacc[nt][1] = -1e30f;
                if (mr1[c0] == 0)     sacc[nt][2] = -1e30f;
                if (mr1[c0 + 1] == 0) sacc[nt][3] = -1e30f;
            }
        }

        // --- log2-domain register online softmax (rows r0 = lane/4, r1 = r0+8) --
        float mx0 = -1e30f, mx1 = -1e30f;
#pragma unroll
        for (int nt = 0; nt < 16; nt++) {
            mx0 = fmaxf(mx0, fmaxf(sacc[nt][0], sacc[nt][1]));
            mx1 = fmaxf(mx1, fmaxf(sacc[nt][2], sacc[nt][3]));
        }
        mx0 = fmaxf(mx0, __shfl_xor_sync(0xffffffffu, mx0, 1));
        mx0 = fmaxf(mx0, __shfl_xor_sync(0xffffffffu, mx0, 2));
        mx1 = fmaxf(mx1, __shfl_xor_sync(0xffffffffu, mx1, 1));
        mx1 = fmaxf(mx1, __shfl_xor_sync(0xffffffffu, mx1, 2));
        float mn0 = fmaxf(m0, mx0 * SC2), mn1 = fmaxf(m1, mx1 * SC2);
        float cr0 = ex2f(m0 - mn0), cr1 = ex2f(m1 - mn1);
        float ls0 = 0.f, ls1 = 0.f;
#pragma unroll
        for (int nt = 0; nt < 16; nt++) {
            sacc[nt][0] = ex2f(fmaf(sacc[nt][0], SC2, -mn0)); ls0 += sacc[nt][0];
            sacc[nt][1] = ex2f(fmaf(sacc[nt][1], SC2, -mn0)); ls0 += sacc[nt][1];
            sacc[nt][2] = ex2f(fmaf(sacc[nt][2], SC2, -mn1)); ls1 += sacc[nt][2];
            sacc[nt][3] = ex2f(fmaf(sacc[nt][3], SC2, -mn1)); ls1 += sacc[nt][3];
        }
        ls0 += __shfl_xor_sync(0xffffffffu, ls0, 1);
        ls0 += __shfl_xor_sync(0xffffffffu, ls0, 2);
        ls1 += __shfl_xor_sync(0xffffffffu, ls1, 1);
        ls1 += __shfl_xor_sync(0xffffffffu, ls1, 2);
        l0 = l0 * cr0 + ls0; m0 = mn0;
        l1 = l1 * cr1 + ls1; m1 = mn1;
#pragma unroll
        for (int nt = 0; nt < 8; nt++) {
            oacc[nt][0] *= cr0; oacc[nt][1] *= cr0;
            oacc[nt][2] *= cr1; oacc[nt][3] *= cr1;
        }

        // --- PV: oacc += P @ V over 128 kv rows ---
        uint32_t vbse = s2u(Vs[st]);
#pragma unroll
        for (int k2 = 0; k2 < 8; k2++) {
            uint32_t pa[4] = {
                pack_bf2(sacc[2 * k2][0],     sacc[2 * k2][1]),
                pack_bf2(sacc[2 * k2][2],     sacc[2 * k2][3]),
                pack_bf2(sacc[2 * k2 + 1][0], sacc[2 * k2 + 1][1]),
                pack_bf2(sacc[2 * k2 + 1][2], sacc[2 * k2 + 1][3])
            };
#pragma unroll
            for (int np = 0; np < 4; np++) {
                int row = k2 * 16 + ((j & 1) << 3) + l7;
                uint32_t r[4];
                ldsm4t(r, vbse + sw128(row, np * 2 + (j >> 1)));
                uint32_t b0[2] = { r[0], r[1] };
                uint32_t b1[2] = { r[2], r[3] };
                mma16816(oacc[2 * np], pa, b0);
                mma16816(oacc[2 * np + 1], pa, b1);
            }
        }

        if (kt < SEQ / 128 - 1) { cp_wait0(); __syncthreads(); }
    }
#undef KV_STAGE

    // --- epilogue: normalize + write bf16 [B*S, D] ---
    float inv0 = 1.f / l0, inv1 = 1.f / l1;
    int r4 = lane >> 2, c2 = (lane & 3) * 2;
    int s0 = qt * 64 + warp * 16 + r4;
#pragma unroll
    for (int nt = 0; nt < 8; nt++) {
        int d = nt * 8 + c2;
        *(uint32_t*)&g_attnb[(size_t)(bb * SEQ + s0) * DMODEL + hh * 64 + d] =
            pack_bf2(oacc[nt][0] * inv0, oacc[nt][1] * inv0);
        *(uint32_t*)&g_attnb[(size_t)(bb * SEQ + s0 + 8) * DMODEL + hh * 64 + d] =
            pack_bf2(oacc[nt][2] * inv1, oacc[nt][3] * inv1);
    }
}

// ---------------- launcher ------------------------------------------------------
extern "C" void kernel_launch(void* const* d_in, const int* in_sizes, int n_in,
                              void* d_out, int out_size) {
    const float* x     = (const float*)d_in[0];
    const int*   mask  = (const int*)d_in[1];
    const float* bq    = (const float*)d_in[3];
    const float* bk    = (const float*)d_in[5];
    const float* bv    = (const float*)d_in[7];
    const float* bo    = (const float*)d_in[9];
    const float* gamma = (const float*)d_in[10];
    const float* beta  = (const float*)d_in[11];
    float* outp = (float*)d_out;

    cudaFuncSetAttribute(attn_kernel, cudaFuncAttributeMaxDynamicSharedMemorySize,
                         ATTN_SMEM);

    ln_kernel<<<MROWS, 256>>>(x, gamma, beta);
    cvt_w_kernel<<<dim3(DMODEL * DMODEL / 1024, 4), 256>>>(
        (const float*)d_in[2], (const float*)d_in[4],
        (const float*)d_in[6], (const float*)d_in[8]);

    mask_scan_kernel<<<BATCH * SEQ * SEQ / 4 / (256 * 8), 256>>>((const int4*)mask);

    gemm_qkv<<<dim3(DMODEL / 128, MROWS / 128, 3), 128>>>(bq, bk, bv);

    attn_kernel<<<dim3(SEQ / 64, NHEAD, BATCH), 128, ATTN_SMEM>>>(mask);

    gemm_out<<<dim3(DMODEL / 128, MROWS / 128), 128>>>(bo, x, outp);
}